// round 1
// baseline (speedup 1.0000x reference)
#include <cuda_runtime.h>
#include <cstdint>

#define NB   64
#define TT   512
#define VV   25
#define CIN  3
#define CH   64
#define FF   25
#define G4   100   // 4*FF

// Scratch (device globals — no allocation allowed)
// zx layout: (n, v, t, 4f) with gate-interleaved columns: col 4*f + k  <->  original gate k*25 + f
// (k: 0=i, 1=f, 2=g~, 3=o).  Bias b_lstm is folded in.
__device__ float g_zx[(size_t)NB * VV * TT * G4];      // 81,920,000 floats = 327.7 MB
// hs layout: (n, t, v, f)
__device__ float g_hs[(size_t)NB * TT * VV * FF];      // 20,480,000 floats = 81.9 MB

__device__ __forceinline__ float hsig(float x) {
    return fminf(fmaxf(fmaf(0.2f, x, 0.5f), 0.0f), 1.0f);
}

// ---------------------------------------------------------------------------
// K1: zx = relu(x @ W_conv + b_conv) @ W_lstm + b_lstm   (gate-interleaved out)
// Block: 256 threads, 40 rows x 100 cols tile. 250 active compute threads
// arranged 25 col-threads (4 cols each) x 10 row-threads (4 rows each).
// ---------------------------------------------------------------------------
__global__ void k1_zx(const float* __restrict__ x,
                      const float* __restrict__ Wc,
                      const float* __restrict__ bc,
                      const float* __restrict__ Wl,
                      const float* __restrict__ bl) {
    __shared__ __align__(16) float xs[120];        // 40 rows x 3
    __shared__ float wcs[192];
    __shared__ float bcs[64];
    __shared__ __align__(16) float u_s[64 * 40];   // [k][row], row-major stride 40
    __shared__ __align__(16) float Ws[64 * 100];   // [k][reordered col]

    const int tid  = threadIdx.x;
    const int row0 = blockIdx.x * 40;

    if (tid < 120) xs[tid] = x[(size_t)row0 * 3 + tid];
    if (tid < 192) wcs[tid] = Wc[tid];
    if (tid >= 192 && tid < 256) bcs[tid - 192] = bc[tid - 192];

    // W_lstm reordered: Ws[k][4*f + kk] = Wl[k][kk*25 + f]
    for (int idx = tid; idx < 6400; idx += 256) {
        int k = idx / 100, j = idx % 100;
        Ws[idx] = Wl[k * 100 + (j & 3) * 25 + (j >> 2)];
    }
    __syncthreads();

    // u = relu(x @ Wc + bc), stored transposed: u_s[ch][row]
    for (int idx = tid; idx < 2560; idx += 256) {
        int ch = idx / 40, r = idx % 40;
        float v = fmaf(xs[r * 3 + 2], wcs[128 + ch],
                  fmaf(xs[r * 3 + 1], wcs[64 + ch],
                  fmaf(xs[r * 3 + 0], wcs[ch], bcs[ch])));
        u_s[ch * 40 + r] = fmaxf(v, 0.0f);
    }
    __syncthreads();

    if (tid < 250) {
        const int ct = tid % 25;   // col group: reordered cols 4*ct .. 4*ct+3
        const int rt = tid / 25;   // row group: rows rt*4 .. rt*4+3

        float4 b4 = make_float4(bl[ct], bl[25 + ct], bl[50 + ct], bl[75 + ct]);
        float4 a0 = b4, a1 = b4, a2 = b4, a3 = b4;

#pragma unroll 8
        for (int k = 0; k < 64; k++) {
            float4 w4 = *reinterpret_cast<const float4*>(&Ws[k * 100 + 4 * ct]);
            float4 u4 = *reinterpret_cast<const float4*>(&u_s[k * 40 + 4 * rt]);
            a0.x = fmaf(u4.x, w4.x, a0.x); a0.y = fmaf(u4.x, w4.y, a0.y);
            a0.z = fmaf(u4.x, w4.z, a0.z); a0.w = fmaf(u4.x, w4.w, a0.w);
            a1.x = fmaf(u4.y, w4.x, a1.x); a1.y = fmaf(u4.y, w4.y, a1.y);
            a1.z = fmaf(u4.y, w4.z, a1.z); a1.w = fmaf(u4.y, w4.w, a1.w);
            a2.x = fmaf(u4.z, w4.x, a2.x); a2.y = fmaf(u4.z, w4.y, a2.y);
            a2.z = fmaf(u4.z, w4.z, a2.z); a2.w = fmaf(u4.z, w4.w, a2.w);
            a3.x = fmaf(u4.w, w4.x, a3.x); a3.y = fmaf(u4.w, w4.y, a3.y);
            a3.z = fmaf(u4.w, w4.z, a3.z); a3.w = fmaf(u4.w, w4.w, a3.w);
        }

#pragma unroll
        for (int ri = 0; ri < 4; ri++) {
            int r   = row0 + rt * 4 + ri;
            int n   = r / (TT * VV);
            int rem = r % (TT * VV);
            int t   = rem / VV;
            int v   = rem % VV;
            size_t zo = (((size_t)(n * VV + v)) * TT + t) * G4 + 4 * ct;
            float4 av = (ri == 0) ? a0 : (ri == 1) ? a1 : (ri == 2) ? a2 : a3;
            *reinterpret_cast<float4*>(&g_zx[zo]) = av;
        }
    }
}

// ---------------------------------------------------------------------------
// K2: LSTM recurrence. One warp per (n,v) sequence. U in registers
// (lane l owns gates {i_l, f_l, g_l, o_l}); h broadcast via shuffle.
// ---------------------------------------------------------------------------
__global__ void __launch_bounds__(128, 3) k2_lstm(const float* __restrict__ U) {
    const int w = threadIdx.x >> 5;
    const int l = threadIdx.x & 31;
    const int s = blockIdx.x * 4 + w;          // sequence id < 1600
    const int n = s / VV, v = s % VV;
    const int li = (l < 25) ? l : 0;

    // Ur[f] = (U[f][l], U[f][25+l], U[f][50+l], U[f][75+l])
    float4 Ur[25];
#pragma unroll
    for (int f = 0; f < 25; f++) {
        Ur[f].x = U[f * 100 + li];
        Ur[f].y = U[f * 100 + 25 + li];
        Ur[f].z = U[f * 100 + 50 + li];
        Ur[f].w = U[f * 100 + 75 + li];
    }

    const float4* zp = reinterpret_cast<const float4*>(g_zx + (size_t)s * TT * G4);
    float4 z0 = zp[0 * 25 + li];
    float4 z1 = zp[1 * 25 + li];

    float c = 0.0f, h = 0.0f;
    float* hout = g_hs + ((size_t)n * TT * VV + v) * FF + li;   // + t*625 per step

    for (int t = 0; t < TT; t++) {
        float4 zc = z0;
        z0 = z1;
        if (t + 2 < TT) z1 = zp[(size_t)(t + 2) * 25 + li];

        float4 aA = make_float4(0.f, 0.f, 0.f, 0.f);
        float4 aB = make_float4(0.f, 0.f, 0.f, 0.f);
#pragma unroll
        for (int f = 0; f < 24; f += 2) {
            float h0 = __shfl_sync(0xffffffffu, h, f);
            float h1 = __shfl_sync(0xffffffffu, h, f + 1);
            aA.x = fmaf(h0, Ur[f].x, aA.x);     aA.y = fmaf(h0, Ur[f].y, aA.y);
            aA.z = fmaf(h0, Ur[f].z, aA.z);     aA.w = fmaf(h0, Ur[f].w, aA.w);
            aB.x = fmaf(h1, Ur[f + 1].x, aB.x); aB.y = fmaf(h1, Ur[f + 1].y, aB.y);
            aB.z = fmaf(h1, Ur[f + 1].z, aB.z); aB.w = fmaf(h1, Ur[f + 1].w, aB.w);
        }
        {
            float h0 = __shfl_sync(0xffffffffu, h, 24);
            aA.x = fmaf(h0, Ur[24].x, aA.x); aA.y = fmaf(h0, Ur[24].y, aA.y);
            aA.z = fmaf(h0, Ur[24].z, aA.z); aA.w = fmaf(h0, Ur[24].w, aA.w);
        }

        float gi = zc.x + aA.x + aB.x;
        float gf = zc.y + aA.y + aB.y;
        float gg = zc.z + aA.z + aB.z;
        float go = zc.w + aA.w + aB.w;

        c = fmaf(hsig(gf), c, hsig(gi) * tanhf(gg));
        h = hsig(go) * tanhf(c);

        if (l < 25) hout[(size_t)t * (VV * FF)] = h;
    }
}

// ---------------------------------------------------------------------------
// K3: per (n,t) tile: recompute x1, softmax(leaky(h)+bias), out = coefs @ x1
// ---------------------------------------------------------------------------
__global__ void k3_out(const float* __restrict__ x,
                       const float* __restrict__ Wc,
                       const float* __restrict__ bc,
                       const float* __restrict__ bias,
                       float* __restrict__ out) {
    __shared__ float es[25 * 26];                  // exp(leaky(h)+bias), padded
    __shared__ float invs[25];
    __shared__ float xs[75];
    __shared__ __align__(16) float x1s[25 * 68];   // [w][c], stride 68 (272B, 16B-aligned)
    __shared__ float wcs[192];
    __shared__ float bcs[64];

    const int nt  = blockIdx.x;
    const int tid = threadIdx.x;

    if (tid < 75)  xs[tid] = x[(size_t)nt * 75 + tid];
    if (tid < 192) wcs[tid] = Wc[tid];
    if (tid >= 192 && tid < 256) bcs[tid - 192] = bc[tid - 192];

    const float* hp = g_hs + (size_t)nt * 625;
    for (int idx = tid; idx < 625; idx += 256) {
        float hv = hp[idx];
        float lv = (hv > 0.0f) ? hv : 0.2f * hv;
        es[(idx / 25) * 26 + (idx % 25)] = __expf(lv + __ldg(bias + idx));
    }
    __syncthreads();

    for (int idx = tid; idx < 1600; idx += 256) {
        int wj = idx >> 6, cc = idx & 63;
        float u = fmaf(xs[wj * 3 + 2], wcs[128 + cc],
                  fmaf(xs[wj * 3 + 1], wcs[64 + cc],
                  fmaf(xs[wj * 3 + 0], wcs[cc], bcs[cc])));
        x1s[wj * 68 + cc] = fmaxf(u, 0.0f);
    }
    if (tid < 25) {
        float sum = 0.0f;
#pragma unroll
        for (int w2 = 0; w2 < 25; w2++) sum += es[tid * 26 + w2];
        invs[tid] = 1.0f / sum;
    }
    __syncthreads();

    float* op = out + (size_t)nt * 1600;
    for (int idx = tid; idx < 400; idx += 256) {
        int vv = idx >> 4, cg = idx & 15;
        float4 acc = make_float4(0.f, 0.f, 0.f, 0.f);
#pragma unroll
        for (int w2 = 0; w2 < 25; w2++) {
            float cf = es[vv * 26 + w2];
            float4 xv = *reinterpret_cast<const float4*>(&x1s[w2 * 68 + 4 * cg]);
            acc.x = fmaf(cf, xv.x, acc.x);
            acc.y = fmaf(cf, xv.y, acc.y);
            acc.z = fmaf(cf, xv.z, acc.z);
            acc.w = fmaf(cf, xv.w, acc.w);
        }
        float iv = invs[vv];
        acc.x *= iv; acc.y *= iv; acc.z *= iv; acc.w *= iv;
        *reinterpret_cast<float4*>(&op[vv * 64 + 4 * cg]) = acc;
    }
}

extern "C" void kernel_launch(void* const* d_in, const int* in_sizes, int n_in,
                              void* d_out, int out_size) {
    const float* x    = (const float*)d_in[0];   // (64,512,25,3)
    const float* Wc   = (const float*)d_in[1];   // (3,64)
    const float* bc   = (const float*)d_in[2];   // (64,)
    const float* Wl   = (const float*)d_in[3];   // (64,100)
    const float* Ul   = (const float*)d_in[4];   // (25,100)
    const float* bl   = (const float*)d_in[5];   // (100,)
    const float* bias = (const float*)d_in[6];   // (25,25)
    float* out = (float*)d_out;                  // (64,512,25,64)

    k1_zx<<<20480, 256>>>(x, Wc, bc, Wl, bl);    // 819200 rows / 40 per block
    k2_lstm<<<400, 128>>>(Ul);                   // 1600 sequences / 4 per block
    k3_out<<<32768, 256>>>(x, Wc, bc, bias, out);
}

// round 3
// speedup vs baseline: 1.1928x; 1.1928x over previous
#include <cuda_runtime.h>
#include <cstdint>

#define NB   64
#define TT   512
#define VV   25
#define CIN  3
#define CH   64
#define FF   25
#define G4   100   // 4*FF

// Scratch (device globals — no allocation allowed)
// zx layout: (n, v, t, 4f) gate-interleaved: col 4*f + k <-> original gate k*25 + f
__device__ float g_zx[(size_t)NB * VV * TT * G4];      // 327.7 MB
// hs layout: (n, t, v, f)
__device__ float g_hs[(size_t)NB * TT * VV * FF];      // 81.9 MB

__device__ __forceinline__ float hsig(float x) {
    return fminf(fmaxf(fmaf(0.2f, x, 0.5f), 0.0f), 1.0f);
}

__device__ __forceinline__ float tanh_fast(float x) {
    float y;
    asm("tanh.approx.f32 %0, %1;" : "=f"(y) : "f"(x));
    return y;
}

// ---------------------------------------------------------------------------
// K1: zx = relu(x @ W_conv + b_conv) @ W_lstm + b_lstm   (gate-interleaved out)
// 40 rows x 100 cols per block; thread = 4 rows x 4 cols.
// Mapping ct = tid/10 keeps w4 loads warp-broadcast (no bank conflicts).
// ---------------------------------------------------------------------------
__global__ void k1_zx(const float* __restrict__ x,
                      const float* __restrict__ Wc,
                      const float* __restrict__ bc,
                      const float* __restrict__ Wl,
                      const float* __restrict__ bl) {
    __shared__ __align__(16) float xs[120];        // 40 rows x 3
    __shared__ float wcs[192];
    __shared__ float bcs[64];
    __shared__ __align__(16) float u_s[64 * 40];   // [k][row]
    __shared__ __align__(16) float Ws[64 * 100];   // [k][reordered col]

    const int tid  = threadIdx.x;
    const int row0 = blockIdx.x * 40;

    if (tid < 120) xs[tid] = x[(size_t)row0 * 3 + tid];
    if (tid < 192) wcs[tid] = Wc[tid];
    if (tid >= 192 && tid < 256) bcs[tid - 192] = bc[tid - 192];

    for (int idx = tid; idx < 6400; idx += 256) {
        int k = idx / 100, j = idx % 100;
        Ws[idx] = Wl[k * 100 + (j & 3) * 25 + (j >> 2)];
    }
    __syncthreads();

    for (int idx = tid; idx < 2560; idx += 256) {
        int ch = idx / 40, r = idx % 40;
        float v = fmaf(xs[r * 3 + 2], wcs[128 + ch],
                  fmaf(xs[r * 3 + 1], wcs[64 + ch],
                  fmaf(xs[r * 3 + 0], wcs[ch], bcs[ch])));
        u_s[ch * 40 + r] = fmaxf(v, 0.0f);
    }
    __syncthreads();

    if (tid < 250) {
        const int ct = tid / 10;   // 0..24: cols 4*ct..4*ct+3  (broadcast in warp)
        const int rt = tid % 10;   // 0..9 : rows rt*4..rt*4+3

        float4 b4 = make_float4(bl[ct], bl[25 + ct], bl[50 + ct], bl[75 + ct]);
        float4 a0 = b4, a1 = b4, a2 = b4, a3 = b4;

#pragma unroll 8
        for (int k = 0; k < 64; k++) {
            float4 w4 = *reinterpret_cast<const float4*>(&Ws[k * 100 + 4 * ct]);
            float4 u4 = *reinterpret_cast<const float4*>(&u_s[k * 40 + 4 * rt]);
            a0.x = fmaf(u4.x, w4.x, a0.x); a0.y = fmaf(u4.x, w4.y, a0.y);
            a0.z = fmaf(u4.x, w4.z, a0.z); a0.w = fmaf(u4.x, w4.w, a0.w);
            a1.x = fmaf(u4.y, w4.x, a1.x); a1.y = fmaf(u4.y, w4.y, a1.y);
            a1.z = fmaf(u4.y, w4.z, a1.z); a1.w = fmaf(u4.y, w4.w, a1.w);
            a2.x = fmaf(u4.z, w4.x, a2.x); a2.y = fmaf(u4.z, w4.y, a2.y);
            a2.z = fmaf(u4.z, w4.z, a2.z); a2.w = fmaf(u4.z, w4.w, a2.w);
            a3.x = fmaf(u4.w, w4.x, a3.x); a3.y = fmaf(u4.w, w4.y, a3.y);
            a3.z = fmaf(u4.w, w4.z, a3.z); a3.w = fmaf(u4.w, w4.w, a3.w);
        }

#pragma unroll
        for (int ri = 0; ri < 4; ri++) {
            int r   = row0 + rt * 4 + ri;
            int n   = r / (TT * VV);
            int rem = r % (TT * VV);
            int t   = rem / VV;
            int v   = rem % VV;
            size_t zo = (((size_t)(n * VV + v)) * TT + t) * G4 + 4 * ct;
            float4 av = (ri == 0) ? a0 : (ri == 1) ? a1 : (ri == 2) ? a2 : a3;
            *reinterpret_cast<float4*>(&g_zx[zo]) = av;
        }
    }
}

// ---------------------------------------------------------------------------
// K2: LSTM recurrence. One warp (block) per (n,v) sequence. U in registers,
// h broadcast via shuffle, 4 accumulators, HW tanh.approx.
// ---------------------------------------------------------------------------
__global__ void __launch_bounds__(32, 12) k2_lstm(const float* __restrict__ U) {
    const int l = threadIdx.x & 31;
    const int s = blockIdx.x;                  // sequence id < 1600
    const int n = s / VV, v = s % VV;
    const int li = (l < 25) ? l : 0;

    float4 Ur[25];
#pragma unroll
    for (int f = 0; f < 25; f++) {
        Ur[f].x = U[f * 100 + li];
        Ur[f].y = U[f * 100 + 25 + li];
        Ur[f].z = U[f * 100 + 50 + li];
        Ur[f].w = U[f * 100 + 75 + li];
    }

    const float4* zp = reinterpret_cast<const float4*>(g_zx + (size_t)s * TT * G4);
    float4 z0 = zp[li];
    float4 z1 = zp[25 + li];

    float c = 0.0f, h = 0.0f;
    float* hout = g_hs + ((size_t)n * TT * VV + v) * FF + li;   // + t*625 per step

    for (int t = 0; t < TT; t++) {
        float4 zc = z0;
        z0 = z1;
        int tn = (t + 2 < TT) ? (t + 2) : (TT - 1);
        z1 = zp[(size_t)tn * 25 + li];

        float4 aA = make_float4(0.f, 0.f, 0.f, 0.f);
        float4 aB = make_float4(0.f, 0.f, 0.f, 0.f);
        float4 aC = make_float4(0.f, 0.f, 0.f, 0.f);
        float4 aD = make_float4(0.f, 0.f, 0.f, 0.f);
#pragma unroll
        for (int f = 0; f < 24; f += 4) {
            float h0 = __shfl_sync(0xffffffffu, h, f);
            float h1 = __shfl_sync(0xffffffffu, h, f + 1);
            float h2 = __shfl_sync(0xffffffffu, h, f + 2);
            float h3 = __shfl_sync(0xffffffffu, h, f + 3);
            aA.x = fmaf(h0, Ur[f].x, aA.x);     aA.y = fmaf(h0, Ur[f].y, aA.y);
            aA.z = fmaf(h0, Ur[f].z, aA.z);     aA.w = fmaf(h0, Ur[f].w, aA.w);
            aB.x = fmaf(h1, Ur[f + 1].x, aB.x); aB.y = fmaf(h1, Ur[f + 1].y, aB.y);
            aB.z = fmaf(h1, Ur[f + 1].z, aB.z); aB.w = fmaf(h1, Ur[f + 1].w, aB.w);
            aC.x = fmaf(h2, Ur[f + 2].x, aC.x); aC.y = fmaf(h2, Ur[f + 2].y, aC.y);
            aC.z = fmaf(h2, Ur[f + 2].z, aC.z); aC.w = fmaf(h2, Ur[f + 2].w, aC.w);
            aD.x = fmaf(h3, Ur[f + 3].x, aD.x); aD.y = fmaf(h3, Ur[f + 3].y, aD.y);
            aD.z = fmaf(h3, Ur[f + 3].z, aD.z); aD.w = fmaf(h3, Ur[f + 3].w, aD.w);
        }
        {
            float h0 = __shfl_sync(0xffffffffu, h, 24);
            aA.x = fmaf(h0, Ur[24].x, aA.x); aA.y = fmaf(h0, Ur[24].y, aA.y);
            aA.z = fmaf(h0, Ur[24].z, aA.z); aA.w = fmaf(h0, Ur[24].w, aA.w);
        }

        float gi = zc.x + ((aA.x + aB.x) + (aC.x + aD.x));
        float gf = zc.y + ((aA.y + aB.y) + (aC.y + aD.y));
        float gg = zc.z + ((aA.z + aB.z) + (aC.z + aD.z));
        float go = zc.w + ((aA.w + aB.w) + (aC.w + aD.w));

        c = fmaf(hsig(gf), c, hsig(gi) * tanh_fast(gg));
        h = hsig(go) * tanh_fast(c);

        if (l < 25) hout[(size_t)t * (VV * FF)] = h;
    }
}

// ---------------------------------------------------------------------------
// K3: 2 (n,t) tiles per 256-block. Per tile: recompute x1, softmax weights,
// then 25x64 = (25x25)@(25x64) GEMM with 5v x 4c register blocking.
// ---------------------------------------------------------------------------
__global__ void k3_out(const float* __restrict__ x,
                       const float* __restrict__ Wc,
                       const float* __restrict__ bc,
                       const float* __restrict__ bias,
                       float* __restrict__ out) {
    __shared__ float wcs[192];
    __shared__ float bcs[64];
    __shared__ float es[2][25 * 26];
    __shared__ float invs[2][32];
    __shared__ float xs[2][80];
    __shared__ __align__(16) float x1s[2][25 * 68];

    const int tid  = threadIdx.x;
    const int half = tid >> 7;
    const int t2   = tid & 127;
    const size_t nt = (size_t)blockIdx.x * 2 + half;

    if (tid < 192) wcs[tid] = Wc[tid];
    if (tid >= 192 && tid < 256) bcs[tid - 192] = bc[tid - 192];
    if (t2 < 75) xs[half][t2] = x[nt * 75 + t2];

    const float* hp = g_hs + nt * 625;
    for (int idx = t2; idx < 625; idx += 128) {
        float hv = hp[idx];
        float lv = (hv > 0.0f) ? hv : 0.2f * hv;
        es[half][(idx / 25) * 26 + (idx % 25)] = __expf(lv + __ldg(bias + idx));
    }
    __syncthreads();

    if (t2 < 25) {
        float sum = 0.0f;
#pragma unroll
        for (int w2 = 0; w2 < 25; w2++) sum += es[half][t2 * 26 + w2];
        invs[half][t2] = 1.0f / sum;
    }
    for (int idx = t2; idx < 1600; idx += 128) {
        int wj = idx >> 6, cc = idx & 63;
        float u = fmaf(xs[half][wj * 3 + 2], wcs[128 + cc],
                  fmaf(xs[half][wj * 3 + 1], wcs[64 + cc],
                  fmaf(xs[half][wj * 3 + 0], wcs[cc], bcs[cc])));
        x1s[half][wj * 68 + cc] = fmaxf(u, 0.0f);
    }
    __syncthreads();

    if (t2 < 80) {
        const int vg = t2 / 16;   // 5 rows: v = vg*5 .. vg*5+4
        const int cg = t2 % 16;   // cols 4*cg .. 4*cg+3

        float4 a0 = make_float4(0.f, 0.f, 0.f, 0.f);
        float4 a1 = a0, a2 = a0, a3 = a0, a4 = a0;
#pragma unroll
        for (int w2 = 0; w2 < 25; w2++) {
            float4 xv = *reinterpret_cast<const float4*>(&x1s[half][w2 * 68 + 4 * cg]);
            float e0 = es[half][(vg * 5 + 0) * 26 + w2];
            float e1 = es[half][(vg * 5 + 1) * 26 + w2];
            float e2 = es[half][(vg * 5 + 2) * 26 + w2];
            float e3 = es[half][(vg * 5 + 3) * 26 + w2];
            float e4 = es[half][(vg * 5 + 4) * 26 + w2];
            a0.x = fmaf(e0, xv.x, a0.x); a0.y = fmaf(e0, xv.y, a0.y);
            a0.z = fmaf(e0, xv.z, a0.z); a0.w = fmaf(e0, xv.w, a0.w);
            a1.x = fmaf(e1, xv.x, a1.x); a1.y = fmaf(e1, xv.y, a1.y);
            a1.z = fmaf(e1, xv.z, a1.z); a1.w = fmaf(e1, xv.w, a1.w);
            a2.x = fmaf(e2, xv.x, a2.x); a2.y = fmaf(e2, xv.y, a2.y);
            a2.z = fmaf(e2, xv.z, a2.z); a2.w = fmaf(e2, xv.w, a2.w);
            a3.x = fmaf(e3, xv.x, a3.x); a3.y = fmaf(e3, xv.y, a3.y);
            a3.z = fmaf(e3, xv.z, a3.z); a3.w = fmaf(e3, xv.w, a3.w);
            a4.x = fmaf(e4, xv.x, a4.x); a4.y = fmaf(e4, xv.y, a4.y);
            a4.z = fmaf(e4, xv.z, a4.z); a4.w = fmaf(e4, xv.w, a4.w);
        }

        float* op = out + nt * 1600;
#pragma unroll
        for (int j = 0; j < 5; j++) {
            int vv = vg * 5 + j;
            float iv = invs[half][vv];
            float4 av = (j == 0) ? a0 : (j == 1) ? a1 : (j == 2) ? a2 : (j == 3) ? a3 : a4;
            av.x *= iv; av.y *= iv; av.z *= iv; av.w *= iv;
            *reinterpret_cast<float4*>(&op[vv * 64 + 4 * cg]) = av;
        }
    }
}

extern "C" void kernel_launch(void* const* d_in, const int* in_sizes, int n_in,
                              void* d_out, int out_size) {
    const float* x    = (const float*)d_in[0];
    const float* Wc   = (const float*)d_in[1];
    const float* bc   = (const float*)d_in[2];
    const float* Wl   = (const float*)d_in[3];
    const float* Ul   = (const float*)d_in[4];
    const float* bl   = (const float*)d_in[5];
    const float* bias = (const float*)d_in[6];
    float* out = (float*)d_out;

    k1_zx<<<20480, 256>>>(x, Wc, bc, Wl, bl);
    k2_lstm<<<1600, 32>>>(Ul);
    k3_out<<<16384, 256>>>(x, Wc, bc, bias, out);
}

// round 4
// speedup vs baseline: 1.3644x; 1.1438x over previous
#include <cuda_runtime.h>
#include <cuda_fp16.h>
#include <cstdint>

#define NB   64
#define TT   512
#define VV   25
#define CIN  3
#define CH   64
#define FF   25
#define G4   100   // 4*FF

// Scratch (device globals — no allocation allowed)
// zx layout: (n, v, t, 4f) gate-interleaved, fp16: col 4*f + k <-> original gate k*25 + f
__device__ __half g_zx_h[(size_t)NB * VV * TT * G4];   // 163.8 MB
// hs layout: (n, t, v, f)
__device__ float g_hs[(size_t)NB * TT * VV * FF];      // 81.9 MB

__device__ __forceinline__ float hsig(float x) {
    return fminf(fmaxf(fmaf(0.2f, x, 0.5f), 0.0f), 1.0f);
}

__device__ __forceinline__ float tanh_fast(float x) {
    float y;
    asm("tanh.approx.f32 %0, %1;" : "=f"(y) : "f"(x));
    return y;
}

__device__ __forceinline__ uint2 pack_half4(float a, float b, float c, float d) {
    __half2 lo = __floats2half2_rn(a, b);
    __half2 hi = __floats2half2_rn(c, d);
    uint2 r;
    r.x = *reinterpret_cast<uint32_t*>(&lo);
    r.y = *reinterpret_cast<uint32_t*>(&hi);
    return r;
}

// ---------------------------------------------------------------------------
// K1: zx = relu(x @ Wc + bc) @ Wl + bl  (gate-interleaved, fp16 out)
// Block: 224 threads (7 warps), tile 32 rows x 100 cols.
// Warps 0-5: 8rt x 4ct layout, thread = 4 rows x 4 cols (cols 0..95).
//   u4: k*32+4*rt -> words {4*rt}, one perfect conflict-free wavefront.
//   w4: 4 distinct float4 (64B), conflict-free.
// Warp 6 (edge): lane = row, 4 scalar cols 96..99; u LDS.32 conflict-free.
// ---------------------------------------------------------------------------
__global__ void __launch_bounds__(224) k1_zx(const float* __restrict__ x,
                      const float* __restrict__ Wc,
                      const float* __restrict__ bc,
                      const float* __restrict__ Wl,
                      const float* __restrict__ bl) {
    __shared__ __align__(16) float xs[96];         // 32 rows x 3
    __shared__ float wcs[192];
    __shared__ float bcs[64];
    __shared__ __align__(16) float u_s[64 * 32];   // [k][row], stride 32
    __shared__ __align__(16) float Ws[64 * 100];   // [k][reordered col]

    const int tid  = threadIdx.x;
    const int row0 = blockIdx.x * 32;

    if (tid < 96)  xs[tid]  = x[(size_t)row0 * 3 + tid];
    if (tid < 192) wcs[tid] = Wc[tid];
    if (tid < 64)  bcs[tid] = bc[tid];

    // Ws[k][4*f + kk] = Wl[k][kk*25 + f]
    for (int idx = tid; idx < 6400; idx += 224) {
        int k = idx / 100, j = idx % 100;
        Ws[idx] = Wl[k * 100 + (j & 3) * 25 + (j >> 2)];
    }
    __syncthreads();

    // u = relu(x @ Wc + bc), transposed: u_s[ch][row]
    for (int idx = tid; idx < 2048; idx += 224) {
        int ch = idx >> 5, r = idx & 31;
        float v = fmaf(xs[r * 3 + 2], wcs[128 + ch],
                  fmaf(xs[r * 3 + 1], wcs[64 + ch],
                  fmaf(xs[r * 3 + 0], wcs[ch], bcs[ch])));
        u_s[ch * 32 + r] = fmaxf(v, 0.0f);
    }
    __syncthreads();

    const int w    = tid >> 5;
    const int lane = tid & 31;

    if (w < 6) {
        const int rt  = lane >> 2;            // 0..7  -> rows rt*4..rt*4+3
        const int ct4 = w * 4 + (lane & 3);   // 0..23 -> feature, cols 4*ct4..+3

        float4 b4 = make_float4(bl[ct4], bl[25 + ct4], bl[50 + ct4], bl[75 + ct4]);
        float4 a0 = b4, a1 = b4, a2 = b4, a3 = b4;

#pragma unroll 8
        for (int k = 0; k < 64; k++) {
            float4 w4 = *reinterpret_cast<const float4*>(&Ws[k * 100 + 4 * ct4]);
            float4 u4 = *reinterpret_cast<const float4*>(&u_s[k * 32 + 4 * rt]);
            a0.x = fmaf(u4.x, w4.x, a0.x); a0.y = fmaf(u4.x, w4.y, a0.y);
            a0.z = fmaf(u4.x, w4.z, a0.z); a0.w = fmaf(u4.x, w4.w, a0.w);
            a1.x = fmaf(u4.y, w4.x, a1.x); a1.y = fmaf(u4.y, w4.y, a1.y);
            a1.z = fmaf(u4.y, w4.z, a1.z); a1.w = fmaf(u4.y, w4.w, a1.w);
            a2.x = fmaf(u4.z, w4.x, a2.x); a2.y = fmaf(u4.z, w4.y, a2.y);
            a2.z = fmaf(u4.z, w4.z, a2.z); a2.w = fmaf(u4.z, w4.w, a2.w);
            a3.x = fmaf(u4.w, w4.x, a3.x); a3.y = fmaf(u4.w, w4.y, a3.y);
            a3.z = fmaf(u4.w, w4.z, a3.z); a3.w = fmaf(u4.w, w4.w, a3.w);
        }

#pragma unroll
        for (int ri = 0; ri < 4; ri++) {
            int r   = row0 + rt * 4 + ri;
            int n   = r / (TT * VV);
            int rem = r % (TT * VV);
            int t   = rem / VV;
            int v   = rem % VV;
            size_t zo = (((size_t)(n * VV + v)) * TT + t) * G4 + 4 * ct4;
            float4 av = (ri == 0) ? a0 : (ri == 1) ? a1 : (ri == 2) ? a2 : a3;
            *reinterpret_cast<uint2*>(&g_zx_h[zo]) =
                pack_half4(av.x, av.y, av.z, av.w);
        }
    } else {
        // edge warp: cols 96..99 (feature 24), lane = row
        float4 acc = make_float4(bl[24], bl[49], bl[74], bl[99]);
#pragma unroll 8
        for (int k = 0; k < 64; k++) {
            float4 w4 = *reinterpret_cast<const float4*>(&Ws[k * 100 + 96]);
            float us  = u_s[k * 32 + lane];
            acc.x = fmaf(us, w4.x, acc.x); acc.y = fmaf(us, w4.y, acc.y);
            acc.z = fmaf(us, w4.z, acc.z); acc.w = fmaf(us, w4.w, acc.w);
        }
        int r   = row0 + lane;
        int n   = r / (TT * VV);
        int rem = r % (TT * VV);
        int t   = rem / VV;
        int v   = rem % VV;
        size_t zo = (((size_t)(n * VV + v)) * TT + t) * G4 + 96;
        *reinterpret_cast<uint2*>(&g_zx_h[zo]) =
            pack_half4(acc.x, acc.y, acc.z, acc.w);
    }
}

// ---------------------------------------------------------------------------
// K2: LSTM recurrence. One warp per (n,v) sequence. U in registers,
// h broadcast via shuffle, 4 accumulators, HW tanh.approx, fp16 zx input.
// ---------------------------------------------------------------------------
__global__ void __launch_bounds__(32, 12) k2_lstm(const float* __restrict__ U) {
    const int l = threadIdx.x & 31;
    const int s = blockIdx.x;                  // sequence id < 1600
    const int n = s / VV, v = s % VV;
    const int li = (l < 25) ? l : 0;

    float4 Ur[25];
#pragma unroll
    for (int f = 0; f < 25; f++) {
        Ur[f].x = U[f * 100 + li];
        Ur[f].y = U[f * 100 + 25 + li];
        Ur[f].z = U[f * 100 + 50 + li];
        Ur[f].w = U[f * 100 + 75 + li];
    }

    // each uint2 = 4 halfs; row = 25 uint2
    const uint2* zp = reinterpret_cast<const uint2*>(g_zx_h + (size_t)s * TT * G4);
    uint2 z0 = zp[li];
    uint2 z1 = zp[25 + li];

    float c = 0.0f, h = 0.0f;
    float* hout = g_hs + ((size_t)n * TT * VV + v) * FF + li;

    for (int t = 0; t < TT; t++) {
        uint2 zc = z0;
        z0 = z1;
        int tn = (t + 2 < TT) ? (t + 2) : (TT - 1);
        z1 = zp[(size_t)tn * 25 + li];

        float4 aA = make_float4(0.f, 0.f, 0.f, 0.f);
        float4 aB = make_float4(0.f, 0.f, 0.f, 0.f);
        float4 aC = make_float4(0.f, 0.f, 0.f, 0.f);
        float4 aD = make_float4(0.f, 0.f, 0.f, 0.f);
#pragma unroll
        for (int f = 0; f < 24; f += 4) {
            float h0 = __shfl_sync(0xffffffffu, h, f);
            float h1 = __shfl_sync(0xffffffffu, h, f + 1);
            float h2 = __shfl_sync(0xffffffffu, h, f + 2);
            float h3 = __shfl_sync(0xffffffffu, h, f + 3);
            aA.x = fmaf(h0, Ur[f].x, aA.x);     aA.y = fmaf(h0, Ur[f].y, aA.y);
            aA.z = fmaf(h0, Ur[f].z, aA.z);     aA.w = fmaf(h0, Ur[f].w, aA.w);
            aB.x = fmaf(h1, Ur[f + 1].x, aB.x); aB.y = fmaf(h1, Ur[f + 1].y, aB.y);
            aB.z = fmaf(h1, Ur[f + 1].z, aB.z); aB.w = fmaf(h1, Ur[f + 1].w, aB.w);
            aC.x = fmaf(h2, Ur[f + 2].x, aC.x); aC.y = fmaf(h2, Ur[f + 2].y, aC.y);
            aC.z = fmaf(h2, Ur[f + 2].z, aC.z); aC.w = fmaf(h2, Ur[f + 2].w, aC.w);
            aD.x = fmaf(h3, Ur[f + 3].x, aD.x); aD.y = fmaf(h3, Ur[f + 3].y, aD.y);
            aD.z = fmaf(h3, Ur[f + 3].z, aD.z); aD.w = fmaf(h3, Ur[f + 3].w, aD.w);
        }
        {
            float h0 = __shfl_sync(0xffffffffu, h, 24);
            aA.x = fmaf(h0, Ur[24].x, aA.x); aA.y = fmaf(h0, Ur[24].y, aA.y);
            aA.z = fmaf(h0, Ur[24].z, aA.z); aA.w = fmaf(h0, Ur[24].w, aA.w);
        }

        __half2 hlo = *reinterpret_cast<__half2*>(&zc.x);
        __half2 hhi = *reinterpret_cast<__half2*>(&zc.y);
        float2 f01 = __half22float2(hlo);
        float2 f23 = __half22float2(hhi);

        float gi = f01.x + ((aA.x + aB.x) + (aC.x + aD.x));
        float gf = f01.y + ((aA.y + aB.y) + (aC.y + aD.y));
        float gg = f23.x + ((aA.z + aB.z) + (aC.z + aD.z));
        float go = f23.y + ((aA.w + aB.w) + (aC.w + aD.w));

        c = fmaf(hsig(gf), c, hsig(gi) * tanh_fast(gg));
        h = hsig(go) * tanh_fast(c);

        if (l < 25) hout[(size_t)t * (VV * FF)] = h;
    }
}

// ---------------------------------------------------------------------------
// K3: 2 (n,t) tiles per 256-block. Per tile: recompute x1, softmax weights,
// then (25x25)@(25x64) GEMM with 5v x 4c register blocking.
// ---------------------------------------------------------------------------
__global__ void k3_out(const float* __restrict__ x,
                       const float* __restrict__ Wc,
                       const float* __restrict__ bc,
                       const float* __restrict__ bias,
                       float* __restrict__ out) {
    __shared__ float wcs[192];
    __shared__ float bcs[64];
    __shared__ float es[2][25 * 26];
    __shared__ float invs[2][32];
    __shared__ float xs[2][80];
    __shared__ __align__(16) float x1s[2][25 * 68];

    const int tid  = threadIdx.x;
    const int half = tid >> 7;
    const int t2   = tid & 127;
    const size_t nt = (size_t)blockIdx.x * 2 + half;

    if (tid < 192) wcs[tid] = Wc[tid];
    if (tid >= 192 && tid < 256) bcs[tid - 192] = bc[tid - 192];
    if (t2 < 75) xs[half][t2] = x[nt * 75 + t2];

    const float* hp = g_hs + nt * 625;
    for (int idx = t2; idx < 625; idx += 128) {
        float hv = hp[idx];
        float lv = (hv > 0.0f) ? hv : 0.2f * hv;
        es[half][(idx / 25) * 26 + (idx % 25)] = __expf(lv + __ldg(bias + idx));
    }
    __syncthreads();

    if (t2 < 25) {
        float sum = 0.0f;
#pragma unroll
        for (int w2 = 0; w2 < 25; w2++) sum += es[half][t2 * 26 + w2];
        invs[half][t2] = 1.0f / sum;
    }
    for (int idx = t2; idx < 1600; idx += 128) {
        int wj = idx >> 6, cc = idx & 63;
        float u = fmaf(xs[half][wj * 3 + 2], wcs[128 + cc],
                  fmaf(xs[half][wj * 3 + 1], wcs[64 + cc],
                  fmaf(xs[half][wj * 3 + 0], wcs[cc], bcs[cc])));
        x1s[half][wj * 68 + cc] = fmaxf(u, 0.0f);
    }
    __syncthreads();

    if (t2 < 80) {
        const int vg = t2 / 16;
        const int cg = t2 % 16;

        float4 a0 = make_float4(0.f, 0.f, 0.f, 0.f);
        float4 a1 = a0, a2 = a0, a3 = a0, a4 = a0;
#pragma unroll
        for (int w2 = 0; w2 < 25; w2++) {
            float4 xv = *reinterpret_cast<const float4*>(&x1s[half][w2 * 68 + 4 * cg]);
            float e0 = es[half][(vg * 5 + 0) * 26 + w2];
            float e1 = es[half][(vg * 5 + 1) * 26 + w2];
            float e2 = es[half][(vg * 5 + 2) * 26 + w2];
            float e3 = es[half][(vg * 5 + 3) * 26 + w2];
            float e4 = es[half][(vg * 5 + 4) * 26 + w2];
            a0.x = fmaf(e0, xv.x, a0.x); a0.y = fmaf(e0, xv.y, a0.y);
            a0.z = fmaf(e0, xv.z, a0.z); a0.w = fmaf(e0, xv.w, a0.w);
            a1.x = fmaf(e1, xv.x, a1.x); a1.y = fmaf(e1, xv.y, a1.y);
            a1.z = fmaf(e1, xv.z, a1.z); a1.w = fmaf(e1, xv.w, a1.w);
            a2.x = fmaf(e2, xv.x, a2.x); a2.y = fmaf(e2, xv.y, a2.y);
            a2.z = fmaf(e2, xv.z, a2.z); a2.w = fmaf(e2, xv.w, a2.w);
            a3.x = fmaf(e3, xv.x, a3.x); a3.y = fmaf(e3, xv.y, a3.y);
            a3.z = fmaf(e3, xv.z, a3.z); a3.w = fmaf(e3, xv.w, a3.w);
            a4.x = fmaf(e4, xv.x, a4.x); a4.y = fmaf(e4, xv.y, a4.y);
            a4.z = fmaf(e4, xv.z, a4.z); a4.w = fmaf(e4, xv.w, a4.w);
        }

        float* op = out + nt * 1600;
#pragma unroll
        for (int j = 0; j < 5; j++) {
            int vv = vg * 5 + j;
            float iv = invs[half][vv];
            float4 av = (j == 0) ? a0 : (j == 1) ? a1 : (j == 2) ? a2 : (j == 3) ? a3 : a4;
            av.x *= iv; av.y *= iv; av.z *= iv; av.w *= iv;
            *reinterpret_cast<float4*>(&op[vv * 64 + 4 * cg]) = av;
        }
    }
}

extern "C" void kernel_launch(void* const* d_in, const int* in_sizes, int n_in,
                              void* d_out, int out_size) {
    const float* x    = (const float*)d_in[0];
    const float* Wc   = (const float*)d_in[1];
    const float* bc   = (const float*)d_in[2];
    const float* Wl   = (const float*)d_in[3];
    const float* Ul   = (const float*)d_in[4];
    const float* bl   = (const float*)d_in[5];
    const float* bias = (const float*)d_in[6];
    float* out = (float*)d_out;

    k1_zx<<<25600, 224>>>(x, Wc, bc, Wl, bl);   // 819200 rows / 32 per block
    k2_lstm<<<1600, 32>>>(Ul);
    k3_out<<<16384, 256>>>(x, Wc, bc, bias, out);
}

// round 6
// speedup vs baseline: 1.7992x; 1.3187x over previous
#include <cuda_runtime.h>
#include <cuda_fp16.h>
#include <cstdint>

#define NB   64
#define TT   512
#define VV   25
#define CIN  3
#define CH   64
#define FF   25
#define G4   100   // 4*FF

typedef unsigned long long ull;

// Scratch (device globals — no allocation allowed)
__device__ __half g_zx_h[(size_t)NB * VV * TT * G4];   // 163.8 MB, layout (n,v,t,4f)
__device__ float  g_hs[(size_t)NB * TT * VV * FF];     // 81.9 MB, layout (n,t,v,f)
__device__ float  g_Wr[64 * 100];                      // reordered W_lstm

__device__ __forceinline__ float hsig(float x) {
    return fminf(fmaxf(fmaf(0.2f, x, 0.5f), 0.0f), 1.0f);
}
__device__ __forceinline__ float tanh_fast(float x) {
    float y;
    asm("tanh.approx.f32 %0, %1;" : "=f"(y) : "f"(x));
    return y;
}

// ---- packed fp32x2 helpers (sm_103a) ----
__device__ __forceinline__ ull pk2(float lo, float hi) {
    ull r;
    asm("mov.b64 %0, {%1, %2};" : "=l"(r)
        : "r"(__float_as_uint(lo)), "r"(__float_as_uint(hi)));
    return r;
}
__device__ __forceinline__ void upk2(ull p, float& lo, float& hi) {
    unsigned int a, b;
    asm("mov.b64 {%0, %1}, %2;" : "=r"(a), "=r"(b) : "l"(p));
    lo = __uint_as_float(a); hi = __uint_as_float(b);
}
__device__ __forceinline__ ull fma2(ull a, ull b, ull c) {
    ull d;
    asm("fma.rn.f32x2 %0, %1, %2, %3;" : "=l"(d) : "l"(a), "l"(b), "l"(c));
    return d;
}
__device__ __forceinline__ ull add2(ull a, ull b) {
    ull d;
    asm("add.rn.f32x2 %0, %1, %2;" : "=l"(d) : "l"(a), "l"(b));
    return d;
}
__device__ __forceinline__ ull mul2(ull a, ull b) {
    ull d;
    asm("mul.rn.f32x2 %0, %1, %2;" : "=l"(d) : "l"(a), "l"(b));
    return d;
}

__device__ __forceinline__ uint2 pack_half4(float a, float b, float c, float d) {
    __half2 lo = __floats2half2_rn(a, b);
    __half2 hi = __floats2half2_rn(c, d);
    uint2 r;
    r.x = *reinterpret_cast<uint32_t*>(&lo);
    r.y = *reinterpret_cast<uint32_t*>(&hi);
    return r;
}

// ---------------------------------------------------------------------------
// K0: reorder W_lstm once: Wr[k][4*f + kk] = Wl[k][kk*25 + f]
// ---------------------------------------------------------------------------
__global__ void k0_reorder(const float* __restrict__ Wl) {
    int idx = blockIdx.x * 256 + threadIdx.x;
    if (idx < 6400) {
        int k = idx / 100, j = idx % 100;
        g_Wr[idx] = Wl[k * 100 + (j & 3) * 25 + (j >> 2)];
    }
}

// ---------------------------------------------------------------------------
// K1: zx = relu(x @ Wc + bc) @ Wl + bl  (gate-interleaved, fp16 out)
// Block: 224 threads (7 warps), tile 64 rows x 100 cols.
// Warps 0-5: 8rt x 4ct lanes; thread = 8 rows x 4 cols, f32x2 accumulators.
// Warp 6 (edge): 2 rows x 4 cols per lane, cols 96..99.
// ---------------------------------------------------------------------------
__global__ void __launch_bounds__(224) k1_zx(const float* __restrict__ x,
                      const float* __restrict__ Wc,
                      const float* __restrict__ bc,
                      const float* __restrict__ bl) {
    __shared__ __align__(16) float xs[192];        // 64 rows x 3
    __shared__ float wcs[192];
    __shared__ float bcs[64];
    __shared__ __align__(16) float u_s[64 * 64];   // [k][row], stride 64
    __shared__ __align__(16) float Ws[64 * 100];   // [k][reordered col]

    const int tid  = threadIdx.x;
    const int row0 = blockIdx.x * 64;

    if (tid < 192) xs[tid]  = x[(size_t)row0 * 3 + tid];
    if (tid < 192) wcs[tid] = Wc[tid];
    if (tid < 64)  bcs[tid] = bc[tid];

    // linear vector copy of pre-reordered weights
    {
        const float4* src = reinterpret_cast<const float4*>(g_Wr);
        float4* dst = reinterpret_cast<float4*>(Ws);
        for (int idx = tid; idx < 1600; idx += 224) dst[idx] = src[idx];
    }
    __syncthreads();

    // u = relu(x @ Wc + bc), transposed: u_s[ch][row]
    for (int idx = tid; idx < 4096; idx += 224) {
        int ch = idx >> 6, r = idx & 63;
        float v = fmaf(xs[r * 3 + 2], wcs[128 + ch],
                  fmaf(xs[r * 3 + 1], wcs[64 + ch],
                  fmaf(xs[r * 3 + 0], wcs[ch], bcs[ch])));
        u_s[ch * 64 + r] = fmaxf(v, 0.0f);
    }
    __syncthreads();

    const int w    = tid >> 5;
    const int lane = tid & 31;

    if (w < 6) {
        const int rt  = lane >> 2;            // 0..7 -> rows rt*8 .. rt*8+7
        const int ct4 = w * 4 + (lane & 3);   // 0..23 -> cols 4*ct4 .. +3

        ull b01 = pk2(bl[ct4],      bl[25 + ct4]);
        ull b23 = pk2(bl[50 + ct4], bl[75 + ct4]);
        ull acc0[8], acc1[8];
#pragma unroll
        for (int ri = 0; ri < 8; ri++) { acc0[ri] = b01; acc1[ri] = b23; }

#pragma unroll 8
        for (int k = 0; k < 64; k++) {
            ulonglong2 wp = *reinterpret_cast<const ulonglong2*>(&Ws[k * 100 + 4 * ct4]);
            float4 ua = *reinterpret_cast<const float4*>(&u_s[k * 64 + 8 * rt]);
            float4 ub = *reinterpret_cast<const float4*>(&u_s[k * 64 + 8 * rt + 4]);
            float uv[8] = {ua.x, ua.y, ua.z, ua.w, ub.x, ub.y, ub.z, ub.w};
#pragma unroll
            for (int ri = 0; ri < 8; ri++) {
                ull uu = pk2(uv[ri], uv[ri]);
                acc0[ri] = fma2(uu, wp.x, acc0[ri]);
                acc1[ri] = fma2(uu, wp.y, acc1[ri]);
            }
        }

#pragma unroll
        for (int ri = 0; ri < 8; ri++) {
            int r   = row0 + rt * 8 + ri;
            int n   = r / (TT * VV);
            int rem = r % (TT * VV);
            int t   = rem / VV;
            int v   = rem % VV;
            size_t zo = (((size_t)(n * VV + v)) * TT + t) * G4 + 4 * ct4;
            float g0, g1, g2, g3;
            upk2(acc0[ri], g0, g1);
            upk2(acc1[ri], g2, g3);
            *reinterpret_cast<uint2*>(&g_zx_h[zo]) = pack_half4(g0, g1, g2, g3);
        }
    } else {
        // edge warp: cols 96..99, rows lane and lane+32
        ull bA = pk2(bl[24], bl[49]);
        ull bB = pk2(bl[74], bl[99]);
        ull aA01 = bA, aA23 = bB, aB01 = bA, aB23 = bB;
#pragma unroll 8
        for (int k = 0; k < 64; k++) {
            ulonglong2 wp = *reinterpret_cast<const ulonglong2*>(&Ws[k * 100 + 96]);
            float uaa = u_s[k * 64 + lane];
            float ubb = u_s[k * 64 + 32 + lane];
            ull uA = pk2(uaa, uaa);
            ull uB = pk2(ubb, ubb);
            aA01 = fma2(uA, wp.x, aA01); aA23 = fma2(uA, wp.y, aA23);
            aB01 = fma2(uB, wp.x, aB01); aB23 = fma2(uB, wp.y, aB23);
        }
#pragma unroll
        for (int half2i = 0; half2i < 2; half2i++) {
            int r   = row0 + lane + 32 * half2i;
            int n   = r / (TT * VV);
            int rem = r % (TT * VV);
            int t   = rem / VV;
            int v   = rem % VV;
            size_t zo = (((size_t)(n * VV + v)) * TT + t) * G4 + 96;
            float g0, g1, g2, g3;
            if (half2i == 0) { upk2(aA01, g0, g1); upk2(aA23, g2, g3); }
            else             { upk2(aB01, g0, g1); upk2(aB23, g2, g3); }
            *reinterpret_cast<uint2*>(&g_zx_h[zo]) = pack_half4(g0, g1, g2, g3);
        }
    }
}

// ---------------------------------------------------------------------------
// K2: LSTM recurrence. One warp per (n,v) sequence. U in registers as f32x2
// pairs (i,f)/(g,o); h broadcast via shuffle; FFMA2 halves fma-pipe work.
// ---------------------------------------------------------------------------
__global__ void __launch_bounds__(32, 12) k2_lstm(const float* __restrict__ U) {
    const int l = threadIdx.x & 31;
    const int s = blockIdx.x;                  // sequence id < 1600
    const int n = s / VV, v = s % VV;
    const int li = (l < 25) ? l : 0;

    ull Uif[25], Ugo[25];
#pragma unroll
    for (int f = 0; f < 25; f++) {
        Uif[f] = pk2(U[f * 100 + li],      U[f * 100 + 25 + li]);
        Ugo[f] = pk2(U[f * 100 + 50 + li], U[f * 100 + 75 + li]);
    }

    const uint2* zp = reinterpret_cast<const uint2*>(g_zx_h + (size_t)s * TT * G4);
    uint2 z0 = zp[li];
    uint2 z1 = zp[25 + li];

    float c = 0.0f, h = 0.0f;
    float* hout = g_hs + ((size_t)n * TT * VV + v) * FF + li;

    for (int t = 0; t < TT; t++) {
        uint2 zc = z0;
        z0 = z1;
        int tn = (t + 2 < TT) ? (t + 2) : (TT - 1);
        z1 = zp[(size_t)tn * 25 + li];

        ull aIF0 = 0, aIF1 = 0, aIF2 = 0, aIF3 = 0;
        ull aGO0 = 0, aGO1 = 0, aGO2 = 0, aGO3 = 0;
#pragma unroll
        for (int f = 0; f < 24; f += 4) {
            float h0 = __shfl_sync(0xffffffffu, h, f);
            float h1 = __shfl_sync(0xffffffffu, h, f + 1);
            float h2 = __shfl_sync(0xffffffffu, h, f + 2);
            float h3 = __shfl_sync(0xffffffffu, h, f + 3);
            ull hh0 = pk2(h0, h0), hh1 = pk2(h1, h1);
            ull hh2 = pk2(h2, h2), hh3 = pk2(h3, h3);
            aIF0 = fma2(hh0, Uif[f],     aIF0); aGO0 = fma2(hh0, Ugo[f],     aGO0);
            aIF1 = fma2(hh1, Uif[f + 1], aIF1); aGO1 = fma2(hh1, Ugo[f + 1], aGO1);
            aIF2 = fma2(hh2, Uif[f + 2], aIF2); aGO2 = fma2(hh2, Ugo[f + 2], aGO2);
            aIF3 = fma2(hh3, Uif[f + 3], aIF3); aGO3 = fma2(hh3, Ugo[f + 3], aGO3);
        }
        {
            float h0 = __shfl_sync(0xffffffffu, h, 24);
            ull hh0 = pk2(h0, h0);
            aIF0 = fma2(hh0, Uif[24], aIF0);
            aGO0 = fma2(hh0, Ugo[24], aGO0);
        }

        __half2 hlo = *reinterpret_cast<__half2*>(&zc.x);
        __half2 hhi = *reinterpret_cast<__half2*>(&zc.y);
        float2 f01 = __half22float2(hlo);
        float2 f23 = __half22float2(hhi);

        ull sIF = add2(add2(aIF0, aIF1), add2(aIF2, aIF3));
        ull sGO = add2(add2(aGO0, aGO1), add2(aGO2, aGO3));
        sIF = add2(sIF, pk2(f01.x, f01.y));
        sGO = add2(sGO, pk2(f23.x, f23.y));

        float gi, gf, gg, go;
        upk2(sIF, gi, gf);
        upk2(sGO, gg, go);

        c = fmaf(hsig(gf), c, hsig(gi) * tanh_fast(gg));
        h = hsig(go) * tanh_fast(c);

        if (l < 25) hout[(size_t)t * (VV * FF)] = h;
    }
}

// ---------------------------------------------------------------------------
// K3: 2 (n,t) tiles per 256-block; recompute x1, softmax, (25x25)@(25x64)
// with 5v x 4c register blocking in f32x2.
// ---------------------------------------------------------------------------
__global__ void k3_out(const float* __restrict__ x,
                       const float* __restrict__ Wc,
                       const float* __restrict__ bc,
                       const float* __restrict__ bias,
                       float* __restrict__ out) {
    __shared__ float wcs[192];
    __shared__ float bcs[64];
    __shared__ float es[2][25 * 26];
    __shared__ float invs[2][32];
    __shared__ float xs[2][80];
    __shared__ __align__(16) float x1s[2][25 * 68];

    const int tid  = threadIdx.x;
    const int half = tid >> 7;
    const int t2   = tid & 127;
    const size_t nt = (size_t)blockIdx.x * 2 + half;

    if (tid < 192) wcs[tid] = Wc[tid];
    if (tid >= 192 && tid < 256) bcs[tid - 192] = bc[tid - 192];
    if (t2 < 75) xs[half][t2] = x[nt * 75 + t2];

    const float* hp = g_hs + nt * 625;
    for (int idx = t2; idx < 625; idx += 128) {
        float hv = hp[idx];
        float lv = (hv > 0.0f) ? hv : 0.2f * hv;
        es[half][(idx / 25) * 26 + (idx % 25)] = __expf(lv + __ldg(bias + idx));
    }
    __syncthreads();

    if (t2 < 25) {
        float sum = 0.0f;
#pragma unroll
        for (int w2 = 0; w2 < 25; w2++) sum += es[half][t2 * 26 + w2];
        invs[half][t2] = 1.0f / sum;
    }
    for (int idx = t2; idx < 1600; idx += 128) {
        int wj = idx >> 6, cc = idx & 63;
        float u = fmaf(xs[half][wj * 3 + 2], wcs[128 + cc],
                  fmaf(xs[half][wj * 3 + 1], wcs[64 + cc],
                  fmaf(xs[half][wj * 3 + 0], wcs[cc], bcs[cc])));
        x1s[half][wj * 68 + cc] = fmaxf(u, 0.0f);
    }
    __syncthreads();

    if (t2 < 80) {
        const int vg = t2 / 16;
        const int cg = t2 % 16;

        ull a01[5] = {0, 0, 0, 0, 0};
        ull a23[5] = {0, 0, 0, 0, 0};
#pragma unroll
        for (int w2 = 0; w2 < 25; w2++) {
            ulonglong2 xp = *reinterpret_cast<const ulonglong2*>(&x1s[half][w2 * 68 + 4 * cg]);
#pragma unroll
            for (int j = 0; j < 5; j++) {
                float e = es[half][(vg * 5 + j) * 26 + w2];
                ull ee = pk2(e, e);
                a01[j] = fma2(ee, xp.x, a01[j]);
                a23[j] = fma2(ee, xp.y, a23[j]);
            }
        }

        float* op = out + nt * 1600;
#pragma unroll
        for (int j = 0; j < 5; j++) {
            int vv = vg * 5 + j;
            float iv = invs[half][vv];
            ull ii = pk2(iv, iv);
            ulonglong2 o;
            o.x = mul2(a01[j], ii);
            o.y = mul2(a23[j], ii);
            *reinterpret_cast<ulonglong2*>(&op[vv * 64 + 4 * cg]) = o;
        }
    }
}

extern "C" void kernel_launch(void* const* d_in, const int* in_sizes, int n_in,
                              void* d_out, int out_size) {
    const float* x    = (const float*)d_in[0];
    const float* Wc   = (const float*)d_in[1];
    const float* bc   = (const float*)d_in[2];
    const float* Wl   = (const float*)d_in[3];
    const float* Ul   = (const float*)d_in[4];
    const float* bl   = (const float*)d_in[5];
    const float* bias = (const float*)d_in[6];
    float* out = (float*)d_out;

    k0_reorder<<<25, 256>>>(Wl);
    k1_zx<<<12800, 224>>>(x, Wc, bc, bl);       // 819200 rows / 64 per block
    k2_lstm<<<1600, 32>>>(Ul);
    k3_out<<<16384, 256>>>(x, Wc, bc, bias, out);
}

// round 7
// speedup vs baseline: 1.8656x; 1.0369x over previous
#include <cuda_runtime.h>
#include <cuda_fp16.h>
#include <cstdint>

#define NB   64
#define TT   512
#define VV   25
#define CIN  3
#define CH   64
#define FF   25
#define G4   100   // 4*FF

typedef unsigned long long ull;

// Scratch (device globals — no allocation allowed)
__device__ __half g_zx_h[(size_t)NB * VV * TT * G4];   // 163.8 MB, layout (n,v,t,4f)
__device__ __half g_hs_h[(size_t)NB * TT * VV * FF];   // 41 MB, layout (n,t,v,f)
__device__ float  g_Wr[64 * 100];                      // reordered W_lstm

__device__ __forceinline__ float hsig(float x) {
    return fminf(fmaxf(fmaf(0.2f, x, 0.5f), 0.0f), 1.0f);
}
__device__ __forceinline__ float tanh_fast(float x) {
    float y;
    asm("tanh.approx.f32 %0, %1;" : "=f"(y) : "f"(x));
    return y;
}

// ---- packed fp32x2 helpers (sm_103a) ----
__device__ __forceinline__ ull pk2(float lo, float hi) {
    ull r;
    asm("mov.b64 %0, {%1, %2};" : "=l"(r)
        : "r"(__float_as_uint(lo)), "r"(__float_as_uint(hi)));
    return r;
}
__device__ __forceinline__ void upk2(ull p, float& lo, float& hi) {
    unsigned int a, b;
    asm("mov.b64 {%0, %1}, %2;" : "=r"(a), "=r"(b) : "l"(p));
    lo = __uint_as_float(a); hi = __uint_as_float(b);
}
__device__ __forceinline__ ull fma2(ull a, ull b, ull c) {
    ull d;
    asm("fma.rn.f32x2 %0, %1, %2, %3;" : "=l"(d) : "l"(a), "l"(b), "l"(c));
    return d;
}
__device__ __forceinline__ ull add2(ull a, ull b) {
    ull d;
    asm("add.rn.f32x2 %0, %1, %2;" : "=l"(d) : "l"(a), "l"(b));
    return d;
}

__device__ __forceinline__ uint2 pack_half4(float a, float b, float c, float d) {
    __half2 lo = __floats2half2_rn(a, b);
    __half2 hi = __floats2half2_rn(c, d);
    uint2 r;
    r.x = *reinterpret_cast<uint32_t*>(&lo);
    r.y = *reinterpret_cast<uint32_t*>(&hi);
    return r;
}

// ---------------------------------------------------------------------------
// K0: reorder W_lstm once: Wr[k][4*f + kk] = Wl[k][kk*25 + f]
// ---------------------------------------------------------------------------
__global__ void k0_reorder(const float* __restrict__ Wl) {
    int idx = blockIdx.x * 256 + threadIdx.x;
    if (idx < 6400) {
        int k = idx / 100, j = idx % 100;
        g_Wr[idx] = Wl[k * 100 + (j & 3) * 25 + (j >> 2)];
    }
}

// ---------------------------------------------------------------------------
// K1: zx = relu(x @ Wc + bc) @ Wl + bl  (gate-interleaved, fp16 out)
// 224 threads, tile 64 rows x 100 cols, f32x2 accumulators.
// ---------------------------------------------------------------------------
__global__ void __launch_bounds__(224) k1_zx(const float* __restrict__ x,
                      const float* __restrict__ Wc,
                      const float* __restrict__ bc,
                      const float* __restrict__ bl) {
    __shared__ __align__(16) float xs[192];
    __shared__ float wcs[192];
    __shared__ float bcs[64];
    __shared__ __align__(16) float u_s[64 * 64];
    __shared__ __align__(16) float Ws[64 * 100];

    const int tid  = threadIdx.x;
    const int row0 = blockIdx.x * 64;

    if (tid < 192) xs[tid]  = x[(size_t)row0 * 3 + tid];
    if (tid < 192) wcs[tid] = Wc[tid];
    if (tid < 64)  bcs[tid] = bc[tid];

    {
        const float4* src = reinterpret_cast<const float4*>(g_Wr);
        float4* dst = reinterpret_cast<float4*>(Ws);
        for (int idx = tid; idx < 1600; idx += 224) dst[idx] = src[idx];
    }
    __syncthreads();

    for (int idx = tid; idx < 4096; idx += 224) {
        int ch = idx >> 6, r = idx & 63;
        float v = fmaf(xs[r * 3 + 2], wcs[128 + ch],
                  fmaf(xs[r * 3 + 1], wcs[64 + ch],
                  fmaf(xs[r * 3 + 0], wcs[ch], bcs[ch])));
        u_s[ch * 64 + r] = fmaxf(v, 0.0f);
    }
    __syncthreads();

    const int w    = tid >> 5;
    const int lane = tid & 31;

    if (w < 6) {
        const int rt  = lane >> 2;
        const int ct4 = w * 4 + (lane & 3);

        ull b01 = pk2(bl[ct4],      bl[25 + ct4]);
        ull b23 = pk2(bl[50 + ct4], bl[75 + ct4]);
        ull acc0[8], acc1[8];
#pragma unroll
        for (int ri = 0; ri < 8; ri++) { acc0[ri] = b01; acc1[ri] = b23; }

#pragma unroll 8
        for (int k = 0; k < 64; k++) {
            ulonglong2 wp = *reinterpret_cast<const ulonglong2*>(&Ws[k * 100 + 4 * ct4]);
            float4 ua = *reinterpret_cast<const float4*>(&u_s[k * 64 + 8 * rt]);
            float4 ub = *reinterpret_cast<const float4*>(&u_s[k * 64 + 8 * rt + 4]);
            float uv[8] = {ua.x, ua.y, ua.z, ua.w, ub.x, ub.y, ub.z, ub.w};
#pragma unroll
            for (int ri = 0; ri < 8; ri++) {
                ull uu = pk2(uv[ri], uv[ri]);
                acc0[ri] = fma2(uu, wp.x, acc0[ri]);
                acc1[ri] = fma2(uu, wp.y, acc1[ri]);
            }
        }

#pragma unroll
        for (int ri = 0; ri < 8; ri++) {
            int r   = row0 + rt * 8 + ri;
            int n   = r / (TT * VV);
            int rem = r % (TT * VV);
            int t   = rem / VV;
            int v   = rem % VV;
            size_t zo = (((size_t)(n * VV + v)) * TT + t) * G4 + 4 * ct4;
            float g0, g1, g2, g3;
            upk2(acc0[ri], g0, g1);
            upk2(acc1[ri], g2, g3);
            *reinterpret_cast<uint2*>(&g_zx_h[zo]) = pack_half4(g0, g1, g2, g3);
        }
    } else {
        ull bA = pk2(bl[24], bl[49]);
        ull bB = pk2(bl[74], bl[99]);
        ull aA01 = bA, aA23 = bB, aB01 = bA, aB23 = bB;
#pragma unroll 8
        for (int k = 0; k < 64; k++) {
            ulonglong2 wp = *reinterpret_cast<const ulonglong2*>(&Ws[k * 100 + 96]);
            float uaa = u_s[k * 64 + lane];
            float ubb = u_s[k * 64 + 32 + lane];
            ull uA = pk2(uaa, uaa);
            ull uB = pk2(ubb, ubb);
            aA01 = fma2(uA, wp.x, aA01); aA23 = fma2(uA, wp.y, aA23);
            aB01 = fma2(uB, wp.x, aB01); aB23 = fma2(uB, wp.y, aB23);
        }
#pragma unroll
        for (int half2i = 0; half2i < 2; half2i++) {
            int r   = row0 + lane + 32 * half2i;
            int n   = r / (TT * VV);
            int rem = r % (TT * VV);
            int t   = rem / VV;
            int v   = rem % VV;
            size_t zo = (((size_t)(n * VV + v)) * TT + t) * G4 + 96;
            float g0, g1, g2, g3;
            if (half2i == 0) { upk2(aA01, g0, g1); upk2(aA23, g2, g3); }
            else             { upk2(aB01, g0, g1); upk2(aB23, g2, g3); }
            *reinterpret_cast<uint2*>(&g_zx_h[zo]) = pack_half4(g0, g1, g2, g3);
        }
    }
}

// ---------------------------------------------------------------------------
// K2: LSTM recurrence. One warp per (n,v) sequence. f32x2 gate pairs,
// HW tanh.approx, fp16 zx in / fp16 hs out.
// ---------------------------------------------------------------------------
__global__ void __launch_bounds__(32, 12) k2_lstm(const float* __restrict__ U) {
    const int l = threadIdx.x & 31;
    const int s = blockIdx.x;
    const int n = s / VV, v = s % VV;
    const int li = (l < 25) ? l : 0;

    ull Uif[25], Ugo[25];
#pragma unroll
    for (int f = 0; f < 25; f++) {
        Uif[f] = pk2(U[f * 100 + li],      U[f * 100 + 25 + li]);
        Ugo[f] = pk2(U[f * 100 + 50 + li], U[f * 100 + 75 + li]);
    }

    const uint2* zp = reinterpret_cast<const uint2*>(g_zx_h + (size_t)s * TT * G4);
    uint2 z0 = zp[li];
    uint2 z1 = zp[25 + li];

    float c = 0.0f, h = 0.0f;
    __half* hout = g_hs_h + ((size_t)n * TT * VV + v) * FF + li;

    for (int t = 0; t < TT; t++) {
        uint2 zc = z0;
        z0 = z1;
        int tn = (t + 2 < TT) ? (t + 2) : (TT - 1);
        z1 = zp[(size_t)tn * 25 + li];

        ull aIF0 = 0, aIF1 = 0, aIF2 = 0, aIF3 = 0;
        ull aGO0 = 0, aGO1 = 0, aGO2 = 0, aGO3 = 0;
#pragma unroll
        for (int f = 0; f < 24; f += 4) {
            float h0 = __shfl_sync(0xffffffffu, h, f);
            float h1 = __shfl_sync(0xffffffffu, h, f + 1);
            float h2 = __shfl_sync(0xffffffffu, h, f + 2);
            float h3 = __shfl_sync(0xffffffffu, h, f + 3);
            ull hh0 = pk2(h0, h0), hh1 = pk2(h1, h1);
            ull hh2 = pk2(h2, h2), hh3 = pk2(h3, h3);
            aIF0 = fma2(hh0, Uif[f],     aIF0); aGO0 = fma2(hh0, Ugo[f],     aGO0);
            aIF1 = fma2(hh1, Uif[f + 1], aIF1); aGO1 = fma2(hh1, Ugo[f + 1], aGO1);
            aIF2 = fma2(hh2, Uif[f + 2], aIF2); aGO2 = fma2(hh2, Ugo[f + 2], aGO2);
            aIF3 = fma2(hh3, Uif[f + 3], aIF3); aGO3 = fma2(hh3, Ugo[f + 3], aGO3);
        }
        {
            float h0 = __shfl_sync(0xffffffffu, h, 24);
            ull hh0 = pk2(h0, h0);
            aIF0 = fma2(hh0, Uif[24], aIF0);
            aGO0 = fma2(hh0, Ugo[24], aGO0);
        }

        __half2 hlo = *reinterpret_cast<__half2*>(&zc.x);
        __half2 hhi = *reinterpret_cast<__half2*>(&zc.y);
        float2 f01 = __half22float2(hlo);
        float2 f23 = __half22float2(hhi);

        ull sIF = add2(add2(aIF0, aIF1), add2(aIF2, aIF3));
        ull sGO = add2(add2(aGO0, aGO1), add2(aGO2, aGO3));
        sIF = add2(sIF, pk2(f01.x, f01.y));
        sGO = add2(sGO, pk2(f23.x, f23.y));

        float gi, gf, gg, go;
        upk2(sIF, gi, gf);
        upk2(sGO, gg, go);

        c = fmaf(hsig(gf), c, hsig(gi) * tanh_fast(gg));
        h = hsig(go) * tanh_fast(c);

        if (l < 25) hout[(size_t)t * (VV * FF)] = __float2half_rn(h);
    }
}

// ---------------------------------------------------------------------------
// K3: block = 160 threads = 2 tiles x 80. Per tile: exp(leaky(h)+bias),
// fold 1/rowsum into es, store es pre-duplicated f32x2; x1 recompute;
// GEMM 5v x 4c per thread with zero idle lanes and no packs.
// ---------------------------------------------------------------------------
__global__ void __launch_bounds__(160) k3_out(const float* __restrict__ x,
                       const float* __restrict__ Wc,
                       const float* __restrict__ bc,
                       const float* __restrict__ bias,
                       float* __restrict__ out) {
    __shared__ float wcs[192];
    __shared__ float bcs[64];
    __shared__ float esr[2][25 * 26];               // raw exp values
    __shared__ float xs[2][80];
    __shared__ __align__(16) float x1s[2][25 * 68];
    __shared__ __align__(16) ull es2[2][25 * 26];   // scaled, duplicated pairs

    const int tid  = threadIdx.x;
    const int half = (tid >= 80) ? 1 : 0;
    const int t2   = tid - 80 * half;
    const size_t nt = (size_t)blockIdx.x * 2 + half;

    for (int i = tid; i < 192; i += 160) wcs[i] = Wc[i];
    if (tid >= 96 && tid < 160) bcs[tid - 96] = bc[tid - 96];
    if (t2 < 75) xs[half][t2] = x[nt * 75 + t2];

    const __half* hp = g_hs_h + nt * 625;
    for (int idx = t2; idx < 625; idx += 80) {
        float hv = __half2float(hp[idx]);
        float lv = (hv > 0.0f) ? hv : 0.2f * hv;
        esr[half][(idx / 25) * 26 + (idx % 25)] = __expf(lv + __ldg(bias + idx));
    }
    __syncthreads();

    // 25 threads/tile: rowsum -> inv -> write scaled duplicated pairs.
    if (t2 < 25) {
        float sum = 0.0f;
#pragma unroll
        for (int w2 = 0; w2 < 25; w2++) sum += esr[half][t2 * 26 + w2];
        float inv = 1.0f / sum;
#pragma unroll
        for (int w2 = 0; w2 < 25; w2++) {
            float e = esr[half][t2 * 26 + w2] * inv;
            es2[half][t2 * 26 + w2] = pk2(e, e);
        }
    }
    // all 80: x1 = relu(x @ Wc + bc)
    for (int idx = t2; idx < 1600; idx += 80) {
        int wj = idx >> 6, cc = idx & 63;
        float u = fmaf(xs[half][wj * 3 + 2], wcs[128 + cc],
                  fmaf(xs[half][wj * 3 + 1], wcs[64 + cc],
                  fmaf(xs[half][wj * 3 + 0], wcs[cc], bcs[cc])));
        x1s[half][wj * 68 + cc] = fmaxf(u, 0.0f);
    }
    __syncthreads();

    // GEMM: all 80 threads, 5 rows x 4 cols each.
    {
        const int vg = t2 / 16;        // 0..4 -> rows vg*5 .. vg*5+4
        const int cg = t2 % 16;        // cols 4*cg .. 4*cg+3

        ull a01[5] = {0, 0, 0, 0, 0};
        ull a23[5] = {0, 0, 0, 0, 0};
        const ull* e2 = &es2[half][0];
#pragma unroll
        for (int w2 = 0; w2 < 25; w2++) {
            ulonglong2 xp = *reinterpret_cast<const ulonglong2*>(&x1s[half][w2 * 68 + 4 * cg]);
#pragma unroll
            for (int j = 0; j < 5; j++) {
                ull ee = e2[(vg * 5 + j) * 26 + w2];
                a01[j] = fma2(ee, xp.x, a01[j]);
                a23[j] = fma2(ee, xp.y, a23[j]);
            }
        }

        float* op = out + nt * 1600;
#pragma unroll
        for (int j = 0; j < 5; j++) {
            int vv = vg * 5 + j;
            ulonglong2 o;
            o.x = a01[j];
            o.y = a23[j];
            *reinterpret_cast<ulonglong2*>(&op[vv * 64 + 4 * cg]) = o;
        }
    }
}

extern "C" void kernel_launch(void* const* d_in, const int* in_sizes, int n_in,
                              void* d_out, int out_size) {
    const float* x    = (const float*)d_in[0];
    const float* Wc   = (const float*)d_in[1];
    const float* bc   = (const float*)d_in[2];
    const float* Wl   = (const float*)d_in[3];
    const float* Ul   = (const float*)d_in[4];
    const float* bl   = (const float*)d_in[5];
    const float* bias = (const float*)d_in[6];
    float* out = (float*)d_out;

    k0_reorder<<<25, 256>>>(Wl);
    k1_zx<<<12800, 224>>>(x, Wc, bc, bl);
    k2_lstm<<<1600, 32>>>(Ul);
    k3_out<<<16384, 160>>>(x, Wc, bc, bias, out);
}